// round 8
// baseline (speedup 1.0000x reference)
#include <cuda_runtime.h>
#include <cstdint>

// Spherical harmonics (L_MAX=8), output [N, 81] fp32.
// Persistent CTAs; compute in registers -> STS tile to smem -> ONE TMA bulk
// store (cp.async.bulk) drains the contiguous 41.5KB tile to DRAM async.
// Warps never touch the drain; only hazard is TMA-read-of-smem vs next STS,
// covered by cp.async.bulk.wait_group.read before the STS phase.

#define LMAX 8
#define NSH  81      // (LMAX+1)^2
#define NQ   45      // (LMAX+1)(LMAX+2)/2
#define BLK  128
#define MAX_CTAS (148 * 5)   // 5 CTAs/SM (smem-limited)

__global__ __launch_bounds__(BLK)
void sh_kernel(const float* __restrict__ xyz,
               const float* __restrict__ F,
               float* __restrict__ out,
               int n, int ntiles)
{
    __shared__ __align__(16) float sbuf[BLK * NSH];   // 41472 B; row stride 81 (odd) -> conflict-free STS
    __shared__ float sF[NQ];

    const int tid = threadIdx.x;
    if (tid < NQ) sF[tid] = F[tid];
    __syncthreads();

    // smem u32 address of sbuf for PTX
    unsigned int sbuf_s32;
    asm("{ .reg .u64 t; cvta.to.shared.u64 t, %1; cvt.u32.u64 %0, t; }"
        : "=r"(sbuf_s32) : "l"((const void*)sbuf));

    // Prefetch first tile's xyz
    int t = blockIdx.x;
    float X = 0.f, Y = 0.f, Z = 0.f;
    bool act = false;
    {
        const int i = t * BLK + tid;
        if (t < ntiles && i < n) {
            act = true;
            X = xyz[3 * i + 0];
            Y = xyz[3 * i + 1];
            Z = xyz[3 * i + 2];
        }
    }

    while (t < ntiles) {
        // ---- compute phase: registers only (previous tile's TMA drains async) ----
        float res[NSH];
        if (act) {
            const float rinv = rsqrtf(X * X + Y * Y + Z * Z);
            const float x = X * rinv, y = Y * rinv, z = Z * rinv;

            float Q[NQ];
            Q[0] = 1.0f;
            #pragma unroll
            for (int l = 1; l <= LMAX; ++l) {
                const int tl  = l * (l + 1) / 2;
                const int tl1 = (l - 1) * l / 2;
                const int tl2 = (l - 2) * (l - 1) / 2;
                Q[tl + l]     = -(2.0f * l - 1.0f) * Q[tl1 + l - 1];
                Q[tl + l - 1] = -z * Q[tl + l];
                #pragma unroll
                for (int m = 0; m <= l - 2; ++m) {
                    Q[tl + m] = ((2.0f * l - 1.0f) * z * Q[tl1 + m]
                                 - (float)(l + m - 1) * Q[tl2 + m]) * (1.0f / (float)(l - m));
                }
            }

            float s[LMAX + 1], c[LMAX + 1];
            s[0] = 0.0f; c[0] = 1.0f;
            #pragma unroll
            for (int m = 1; m <= LMAX; ++m) {
                s[m] = x * s[m - 1] + y * c[m - 1];
                c[m] = x * c[m - 1] - y * s[m - 1];
            }

            const float inv_sqrt2 = 0.70710678118654752440f;
            #pragma unroll
            for (int l = 0; l <= LMAX; ++l) {
                const int base = l * (l + 1) / 2;
                const int col0 = l * l;
                #pragma unroll
                for (int m = -l; m < 0; ++m)
                    res[col0 + l + m] = sF[base - m] * Q[base - m] * s[-m];
                res[col0 + l] = sF[base] * Q[base] * inv_sqrt2;
                #pragma unroll
                for (int m = 1; m <= l; ++m)
                    res[col0 + l + m] = sF[base + m] * Q[base + m] * c[m];
            }
        }

        // ---- prefetch next tile's xyz (latency hides under STS + barriers) ----
        const int tn = t + gridDim.x;
        bool actn = false;
        float Xn = 0.f, Yn = 0.f, Zn = 0.f;
        if (tn < ntiles) {
            const int i2 = tn * BLK + tid;
            if (i2 < n) {
                actn = true;
                Xn = xyz[3 * i2 + 0];
                Yn = xyz[3 * i2 + 1];
                Zn = xyz[3 * i2 + 2];
            }
        }

        // ---- ensure previous TMA has finished READING sbuf before overwriting ----
        if (tid == 0)
            asm volatile("cp.async.bulk.wait_group.read 0;" ::: "memory");
        __syncthreads();

        // ---- STS phase ----
        if (act) {
            float* o = &sbuf[tid * NSH];
            #pragma unroll
            for (int k = 0; k < NSH; ++k)
                o[k] = res[k];
        }
        __syncthreads();

        // ---- issue async bulk store of the contiguous tile ----
        {
            const int base_pt = t * BLK;
            const int npts  = min(BLK, n - base_pt);
            const int total = npts * NSH;            // floats
            float* gout = out + (size_t)base_pt * NSH;
            const int nb16 = (total * 4) & ~15;      // bulk bytes (16B granularity)
            if (tid == 0 && nb16 > 0) {
                asm volatile("fence.proxy.async.shared::cta;" ::: "memory");
                asm volatile(
                    "cp.async.bulk.global.shared::cta.bulk_group [%0], [%1], %2;"
                    :: "l"(gout), "r"(sbuf_s32), "r"(nb16) : "memory");
                asm volatile("cp.async.bulk.commit_group;" ::: "memory");
            }
            // scalar tail (never hit when total % 4 == 0; n = 1e6 -> always empty)
            for (int k = (nb16 >> 2) + tid; k < total; k += BLK)
                gout[k] = sbuf[k];
        }

        t = tn; act = actn; X = Xn; Y = Yn; Z = Zn;
    }

    // drain remaining TMA groups before exit
    if (tid == 0)
        asm volatile("cp.async.bulk.wait_group 0;" ::: "memory");
}

extern "C" void kernel_launch(void* const* d_in, const int* in_sizes, int n_in,
                              void* d_out, int out_size)
{
    const float* xyz = (const float*)d_in[0];
    const float* F   = (const float*)d_in[1];
    float* out       = (float*)d_out;
    const int n      = in_sizes[0] / 3;
    if (n <= 0) return;
    const int ntiles = (n + BLK - 1) / BLK;
    const int grid   = ntiles < MAX_CTAS ? ntiles : MAX_CTAS;
    sh_kernel<<<grid, BLK>>>(xyz, F, out, n, ntiles);
}